// round 5
// baseline (speedup 1.0000x reference)
#include <cuda_runtime.h>
#include <cuda_bf16.h>
#include <cstdint>

#define N_MAX 100000
#define E_MAX 600000
#define HF 128

// ---------------- scratch (static __device__ — no allocation) ----------------
__device__ __align__(16) float d_bufA[N_MAX * HF];
__device__ __align__(16) float d_bufB[N_MAX * HF];
__device__ int   d_cnt[N_MAX];
__device__ int   d_incl[N_MAX];
__device__ int   d_rs[N_MAX + 1];
__device__ int   d_cursor[N_MAX];
__device__ int   d_csr[E_MAX];
__device__ float d_dinv[N_MAX];
__device__ float d_sc[N_MAX];     // dinv/deg
__device__ int   d_bsum[256];
__device__ int   d_bpref[256];
// plain row-major bf16 W images (hi/lo) per layer: 128x128 bf16 = 8192 u32
__device__ __align__(16) unsigned d_wimg_hi[4][8192];
__device__ __align__(16) unsigned d_wimg_lo[4][8192];

// ================= warp-MMA helpers (portable on compute_103 base) =================
__device__ __forceinline__ uint32_t smem_u32(const void* p) {
    uint32_t a;
    asm("{ .reg .u64 t; cvta.to.shared.u64 t, %1; cvt.u32.u64 %0, t; }" : "=r"(a) : "l"(p));
    return a;
}
__device__ __forceinline__ void ldmx4(uint32_t& r0, uint32_t& r1, uint32_t& r2, uint32_t& r3,
                                      uint32_t addr) {
    asm volatile("ldmatrix.sync.aligned.m8n8.x4.shared.b16 {%0,%1,%2,%3}, [%4];"
                 : "=r"(r0), "=r"(r1), "=r"(r2), "=r"(r3) : "r"(addr));
}
__device__ __forceinline__ void ldmx2(uint32_t& r0, uint32_t& r1, uint32_t addr) {
    asm volatile("ldmatrix.sync.aligned.m8n8.x2.shared.b16 {%0,%1}, [%2];"
                 : "=r"(r0), "=r"(r1) : "r"(addr));
}
__device__ __forceinline__ void mma16816(float* d, uint32_t a0, uint32_t a1, uint32_t a2,
                                         uint32_t a3, uint32_t b0, uint32_t b1) {
    asm volatile("mma.sync.aligned.m16n8k16.row.col.f32.bf16.bf16.f32 "
                 "{%0,%1,%2,%3},{%4,%5,%6,%7},{%8,%9},{%0,%1,%2,%3};"
                 : "+f"(d[0]), "+f"(d[1]), "+f"(d[2]), "+f"(d[3])
                 : "r"(a0), "r"(a1), "r"(a2), "r"(a3), "r"(b0), "r"(b1));
}
__device__ __forceinline__ unsigned pack_bf(float a, float b) {
    return (unsigned)__bfloat16_as_ushort(__float2bfloat16_rn(a)) |
           ((unsigned)__bfloat16_as_ushort(__float2bfloat16_rn(b)) << 16);
}

// ---------------- preprocessing: CSR-by-target + degree terms ----------------
__global__ void k_init(int n) {
    int i = blockIdx.x * blockDim.x + threadIdx.x;
    if (i < n) d_cnt[i] = 0;
}

__global__ void k_hist(const int* __restrict__ col, int e, int n) {
    int i = blockIdx.x * blockDim.x + threadIdx.x;
    if (i < e) {
        int c = col[i];
        if (c >= 0 && c < n) atomicAdd(&d_cnt[c], 1);
    }
}

__global__ void k_scan1(int n) {
    __shared__ int s[1024];
    int t = threadIdx.x;
    int i = blockIdx.x * 1024 + t;
    s[t] = (i < n) ? d_cnt[i] : 0;
    __syncthreads();
    for (int off = 1; off < 1024; off <<= 1) {
        int a = 0;
        if (t >= off) a = s[t - off];
        __syncthreads();
        s[t] += a;
        __syncthreads();
    }
    if (i < n) d_incl[i] = s[t];
    if (t == 1023) d_bsum[blockIdx.x] = s[1023];
}

__global__ void k_scan2(int nb) {   // single warp, shfl scan with carry
    int lane = threadIdx.x;
    int carry = 0;
    for (int base = 0; base < nb; base += 32) {
        int i = base + lane;
        int own = (i < nb) ? d_bsum[i] : 0;
        int v = own;
        #pragma unroll
        for (int o = 1; o < 32; o <<= 1) {
            int t = __shfl_up_sync(0xffffffffu, v, o);
            if (lane >= o) v += t;
        }
        if (i < nb) d_bpref[i] = carry + v - own;   // exclusive
        carry += __shfl_sync(0xffffffffu, v, 31);
    }
}

__global__ void k_scan3(int n) {
    int i = blockIdx.x * blockDim.x + threadIdx.x;
    if (i >= n) return;
    int gi = d_incl[i] + d_bpref[i >> 10];
    int c  = d_cnt[i];
    int st = gi - c;
    d_rs[i] = st;
    d_cursor[i] = st;
    if (i == n - 1) d_rs[n] = gi;
    float deg = (float)(c + 1);          // degree incl. self-loop
    float di = rsqrtf(deg);
    d_dinv[i] = di;
    d_sc[i]   = di / deg;
}

__global__ void k_scatter(const int* __restrict__ ei, int e, int n) {
    int i = blockIdx.x * blockDim.x + threadIdx.x;
    if (i >= e) return;
    int c = ei[e + i];  // col (target)
    int r = ei[i];      // row (source)
    if (c < 0 || c >= n || r < 0 || r >= n) return;
    int pos = atomicAdd(&d_cursor[c], 1);
    d_csr[pos] = r;
}

// ---------------- W prep: fp32[128][128] -> plain bf16 hi/lo images ----------------
__global__ void __launch_bounds__(256) k_prepw(
    const float* __restrict__ Wa, const float* __restrict__ Wb,
    const float* __restrict__ Wc, const float* __restrict__ Wd)
{
    int l = blockIdx.x;
    const float* W = (l == 0) ? Wa : (l == 1) ? Wb : (l == 2) ? Wc : Wd;
    unsigned* hi = d_wimg_hi[l];
    unsigned* lo = d_wimg_lo[l];
    int tid = threadIdx.x;
    int r = tid >> 1;
    int f40 = (tid & 1) * 16;
    const float4* W4 = (const float4*)W;
    #pragma unroll
    for (int j = 0; j < 16; ++j) {
        int f4 = f40 + j;
        int k = f4 * 4;
        float4 v = W4[r * 32 + f4];
        float hx = __bfloat162float(__float2bfloat16_rn(v.x));
        float hy = __bfloat162float(__float2bfloat16_rn(v.y));
        float hz = __bfloat162float(__float2bfloat16_rn(v.z));
        float hw = __bfloat162float(__float2bfloat16_rn(v.w));
        int i0 = r * 64 + (k >> 1);
        hi[i0 + 0] = pack_bf(v.x, v.y);
        hi[i0 + 1] = pack_bf(v.z, v.w);
        lo[i0 + 0] = pack_bf(v.x - hx, v.y - hy);
        lo[i0 + 1] = pack_bf(v.z - hz, v.w - hw);
    }
}

// ---------------- warp-MMA bf16x3 GEMM: bufB = rs * (A @ W^T + bias), opt relu ----------------
// 128-row x 128-col tile per block, 8 warps, warp w -> rows 16w..16w+15.
// smem: bias[128] f32 @0; 4 bf16 images pitch 136 (pad 8 -> ldmatrix conflict-free).
#define PITCH   136                    // bf16 elements per row
#define IMG_B   (128 * PITCH * 2)      // 34816 bytes per image
#define OFF_AHI 1024
#define OFF_ALO (OFF_AHI + IMG_B)
#define OFF_WHI (OFF_ALO + IMG_B)
#define OFF_WLO (OFF_WHI + IMG_B)
#define SMEM_TOT (OFF_WLO + IMG_B)     // 140288

__global__ void __launch_bounds__(256, 1) k_gemm_mma(
    const float* __restrict__ Aopt,        // nullptr -> d_bufA
    const unsigned* __restrict__ whi,
    const unsigned* __restrict__ wlo,
    const float* __restrict__ bias,
    const float* __restrict__ colscale,    // nullptr or [128]
    int use_dinv, int relu, int n)
{
    extern __shared__ __align__(16) char sm[];
    uint32_t smb = smem_u32(sm);
    int tid = threadIdx.x;
    int wid = tid >> 5, lane = tid & 31;
    int row0 = blockIdx.x * 128;
    const float* A = Aopt ? Aopt : d_bufA;

    // bias -> smem
    if (tid < 128) *(float*)(sm + tid * 4) = bias[tid];

    // W images -> padded smem (row: 16 float4 src -> 17-float4-pitch dst)
    {
        const float4* wh4 = (const float4*)whi;
        const float4* wl4 = (const float4*)wlo;
        float4* dh = (float4*)(sm + OFF_WHI);
        float4* dl = (float4*)(sm + OFF_WLO);
        #pragma unroll
        for (int i = 0; i < 8; ++i) {
            int idx = tid + i * 256;        // 0..2047
            int r = idx >> 4, c4 = idx & 15;
            dh[r * 17 + c4] = wh4[idx];
            dl[r * 17 + c4] = wl4[idx];
        }
    }

    // A tile: load fp32, split into bf16 hi/lo, store padded row-major
    {
        int r = tid >> 1;
        int f40 = (tid & 1) * 16;
        int gr = row0 + r;
        const float4* A4 = (const float4*)A;
        unsigned* ah = (unsigned*)(sm + OFF_AHI);
        unsigned* al = (unsigned*)(sm + OFF_ALO);
        #pragma unroll
        for (int j = 0; j < 16; ++j) {
            int f4 = f40 + j;
            int k = f4 * 4;
            float4 v = make_float4(0.f, 0.f, 0.f, 0.f);
            if (gr < n) v = A4[gr * 32 + f4];
            if (colscale) {
                v.x *= colscale[k + 0];
                v.y *= colscale[k + 1];
                v.z *= colscale[k + 2];
                v.w *= colscale[k + 3];
            }
            float hx = __bfloat162float(__float2bfloat16_rn(v.x));
            float hy = __bfloat162float(__float2bfloat16_rn(v.y));
            float hz = __bfloat162float(__float2bfloat16_rn(v.z));
            float hw = __bfloat162float(__float2bfloat16_rn(v.w));
            int i0 = r * (PITCH / 2) + (k >> 1);
            ah[i0 + 0] = pack_bf(v.x, v.y);
            ah[i0 + 1] = pack_bf(v.z, v.w);
            al[i0 + 0] = pack_bf(v.x - hx, v.y - hy);
            al[i0 + 1] = pack_bf(v.z - hz, v.w - hw);
        }
    }
    __syncthreads();

    // accumulators: 16 n-chunks x 4
    float acc[16][4];
    #pragma unroll
    for (int i = 0; i < 16; i++) {
        acc[i][0] = 0.f; acc[i][1] = 0.f; acc[i][2] = 0.f; acc[i][3] = 0.f;
    }

    // ldmatrix lane addressing (byte offsets within an image)
    int arow = wid * 16 + (lane & 15);
    int acol = (lane >> 4) * 8;
    uint32_t a_lane = (uint32_t)(arow * PITCH + acol) * 2;
    int brow = lane & 7;
    int bcol = ((lane >> 3) & 1) * 8;
    uint32_t b_lane = (uint32_t)(brow * PITCH + bcol) * 2;

    // 3 passes: Ah*Wh, Ah*Wl, Al*Wh
    #pragma unroll
    for (int pass = 0; pass < 3; ++pass) {
        uint32_t abase = smb + (pass == 2 ? OFF_ALO : OFF_AHI) + a_lane;
        uint32_t wbase = smb + (pass == 1 ? OFF_WLO : OFF_WHI) + b_lane;
        #pragma unroll
        for (int kc = 0; kc < 8; ++kc) {
            uint32_t koff = (uint32_t)(kc * 16 * 2);
            uint32_t a0, a1, a2, a3;
            ldmx4(a0, a1, a2, a3, abase + koff);
            #pragma unroll
            for (int nc = 0; nc < 16; ++nc) {
                uint32_t b0, b1;
                ldmx2(b0, b1, wbase + koff + (uint32_t)(nc * 8 * PITCH * 2));
                mma16816(acc[nc], a0, a1, a2, a3, b0, b1);
            }
        }
    }

    // epilogue: d0,d1 -> (row=lane/4, col=2*(lane%4)+{0,1}); d2,d3 -> row+8
    {
        int r0 = row0 + wid * 16 + (lane >> 2);
        int r1 = r0 + 8;
        float rs0 = 1.f, rs1 = 1.f;
        if (use_dinv) {
            if (r0 < n) rs0 = d_dinv[r0];
            if (r1 < n) rs1 = d_dinv[r1];
        }
        const float* bs = (const float*)sm;
        #pragma unroll
        for (int nc = 0; nc < 16; ++nc) {
            int c = nc * 8 + (lane & 3) * 2;
            float bx = bs[c], by = bs[c + 1];
            if (r0 < n) {
                float2 o;
                o.x = (acc[nc][0] + bx) * rs0;
                o.y = (acc[nc][1] + by) * rs0;
                if (relu) { o.x = fmaxf(o.x, 0.f); o.y = fmaxf(o.y, 0.f); }
                *(float2*)(d_bufB + (size_t)r0 * 128 + c) = o;
            }
            if (r1 < n) {
                float2 o;
                o.x = (acc[nc][2] + bx) * rs1;
                o.y = (acc[nc][3] + by) * rs1;
                if (relu) { o.x = fmaxf(o.x, 0.f); o.y = fmaxf(o.y, 0.f); }
                *(float2*)(d_bufB + (size_t)r1 * 128 + c) = o;
            }
        }
    }
}

// ---------------- aggregation: bufA[c] = relu(sc[c]*(bufB[c]+sum bufB[src]) + bc) ----------------
__global__ void k_agg(const float* __restrict__ bc, int n)
{
    int w = (blockIdx.x * blockDim.x + threadIdx.x) >> 5;
    int lane = threadIdx.x & 31;
    if (w >= n) return;
    const float4* g = (const float4*)d_bufB;
    float4 s = g[w * 32 + lane];   // self-loop term
    int beg = d_rs[w], end = d_rs[w + 1];
    for (int e = beg; e < end; ++e) {
        int src = d_csr[e];
        float4 v = g[src * 32 + lane];
        s.x += v.x; s.y += v.y; s.z += v.z; s.w += v.w;
    }
    float kf = d_sc[w];
    float bx = bc[lane * 4 + 0], by = bc[lane * 4 + 1];
    float bz = bc[lane * 4 + 2], bw = bc[lane * 4 + 3];
    float4 o;
    o.x = fmaxf(kf * s.x + bx, 0.f);
    o.y = fmaxf(kf * s.y + by, 0.f);
    o.z = fmaxf(kf * s.z + bz, 0.f);
    o.w = fmaxf(kf * s.w + bw, 0.f);
    ((float4*)d_bufA)[w * 32 + lane] = o;
}

// ---------------- final linear (H=128 -> C=40) + log_softmax, one warp/row ----------------
__global__ void __launch_bounds__(256) k_lin2(
    const float* __restrict__ W2, const float* __restrict__ b2,
    float* __restrict__ out, int n)
{
    __shared__ __align__(16) float Ws[40 * 129];
    __shared__ __align__(16) float rowbuf[8][128];
    int tid = threadIdx.x;
    for (int idx = tid; idx < 40 * 128; idx += 256) {
        int c = idx >> 7, k = idx & 127;
        Ws[c * 129 + k] = W2[idx];
    }
    __syncthreads();

    int lane = tid & 31, w = tid >> 5;
    int row = blockIdx.x * 8 + w;
    if (row >= n) return;

    float4 hv = ((const float4*)d_bufB)[row * 32 + lane];
    rowbuf[w][lane * 4 + 0] = hv.x;
    rowbuf[w][lane * 4 + 1] = hv.y;
    rowbuf[w][lane * 4 + 2] = hv.z;
    rowbuf[w][lane * 4 + 3] = hv.w;
    __syncwarp();

    int c1 = 32 + (lane & 7);
    float v0 = b2[lane];
    float v1 = b2[c1];
    #pragma unroll 8
    for (int k = 0; k < 128; k++) {
        float hk = rowbuf[w][k];
        v0 += hk * Ws[lane * 129 + k];
        v1 += hk * Ws[c1 * 129 + k];
    }
    float m = fmaxf(v0, (lane < 8) ? v1 : -1e30f);
    #pragma unroll
    for (int o = 16; o; o >>= 1) m = fmaxf(m, __shfl_xor_sync(0xffffffffu, m, o));
    float e0 = __expf(v0 - m);
    float e1 = (lane < 8) ? __expf(v1 - m) : 0.f;
    float ssum = e0 + e1;
    #pragma unroll
    for (int o = 16; o; o >>= 1) ssum += __shfl_xor_sync(0xffffffffu, ssum, o);
    float ls = m + __logf(ssum);
    out[row * 40 + lane] = v0 - ls;
    if (lane < 8) out[row * 40 + 32 + lane] = v1 - ls;
}

// ---------------- launch ----------------
extern "C" void kernel_launch(void* const* d_in, const int* in_sizes, int n_in,
                              void* d_out, int out_size)
{
    const float* x    = (const float*)d_in[0];
    const int*   ei   = (const int*)d_in[1];     // int32 (JAX x64 disabled)
    const float* imp  = (const float*)d_in[2];
    const float* W1   = (const float*)d_in[3];
    const float* bl1  = (const float*)d_in[4];
    const float* bc1  = (const float*)d_in[5];
    const float* W2   = (const float*)d_in[6];
    const float* bl2  = (const float*)d_in[7];
    const float* bc2  = (const float*)d_in[8];
    const float* W3   = (const float*)d_in[9];
    const float* bl3  = (const float*)d_in[10];
    const float* bc3  = (const float*)d_in[11];
    const float* Wl1  = (const float*)d_in[12];
    const float* bli1 = (const float*)d_in[13];
    const float* Wl2  = (const float*)d_in[14];
    const float* bli2 = (const float*)d_in[15];
    int n = in_sizes[0] / HF;
    int e = in_sizes[1] / 2;
    float* out = (float*)d_out;

    cudaFuncSetAttribute(k_gemm_mma, cudaFuncAttributeMaxDynamicSharedMemorySize, SMEM_TOT);

    // preprocessing (CSR build + degree scaling) + W bf16-split images
    k_init   <<<(n + 255) / 256, 256>>>(n);
    k_hist   <<<(e + 255) / 256, 256>>>(ei + e, e, n);
    int nb = (n + 1023) / 1024;
    k_scan1  <<<nb, 1024>>>(n);
    k_scan2  <<<1, 32>>>(nb);
    k_scan3  <<<(n + 255) / 256, 256>>>(n);
    k_scatter<<<(e + 255) / 256, 256>>>(ei, e, n);
    k_prepw  <<<4, 256>>>(W1, W2, W3, Wl1);

    int gblocks = (n + 127) / 128;
    int ablocks = (n + 7) / 8;

    // conv1 (importance folded into A split; dinv rowscale in epilogue)
    k_gemm_mma<<<gblocks, 256, SMEM_TOT>>>(x,       d_wimg_hi[0], d_wimg_lo[0], bl1,  imp,     1, 0, n);
    k_agg     <<<ablocks, 256>>>(bc1, n);
    // conv2
    k_gemm_mma<<<gblocks, 256, SMEM_TOT>>>(nullptr, d_wimg_hi[1], d_wimg_lo[1], bl2,  nullptr, 1, 0, n);
    k_agg     <<<ablocks, 256>>>(bc2, n);
    // conv3
    k_gemm_mma<<<gblocks, 256, SMEM_TOT>>>(nullptr, d_wimg_hi[2], d_wimg_lo[2], bl3,  nullptr, 1, 0, n);
    k_agg     <<<ablocks, 256>>>(bc3, n);
    // lin1 + relu
    k_gemm_mma<<<gblocks, 256, SMEM_TOT>>>(nullptr, d_wimg_hi[3], d_wimg_lo[3], bli1, nullptr, 0, 1, n);
    // lin2 + log_softmax
    k_lin2    <<<ablocks, 256>>>(Wl2, bli2, out, n);
}

// round 6
// speedup vs baseline: 1.2023x; 1.2023x over previous
#include <cuda_runtime.h>
#include <cstdint>

#define N_MAX 100000
#define E_MAX 600000
#define HF 128

// ---------------- scratch (static __device__ — no allocation) ----------------
__device__ __align__(16) float d_bufA[N_MAX * HF];
__device__ __align__(16) float d_bufB[N_MAX * HF];
__device__ int   d_cnt[N_MAX];
__device__ int   d_incl[N_MAX];
__device__ int   d_rs[N_MAX + 1];
__device__ int   d_cursor[N_MAX];
__device__ int   d_csr[E_MAX];
__device__ float d_dinv[N_MAX];
__device__ float d_sc[N_MAX];     // dinv/deg
__device__ int   d_bsum[256];
__device__ int   d_bpref[256];
// transposed fp32 W images per layer: wT[k][j] = W[j][k], 128x128
__device__ __align__(16) float d_wimgT[4][16384];

__device__ __forceinline__ uint32_t smem_u32(const void* p) {
    uint32_t a;
    asm("{ .reg .u64 t; cvta.to.shared.u64 t, %1; cvt.u32.u64 %0, t; }" : "=r"(a) : "l"(p));
    return a;
}
__device__ __forceinline__ unsigned long long lds64(uint32_t addr) {
    unsigned long long v;
    asm volatile("ld.shared.b64 %0, [%1];" : "=l"(v) : "r"(addr));
    return v;
}
__device__ __forceinline__ void ffma2(unsigned long long& d, unsigned long long a,
                                      unsigned long long b) {
    asm volatile("fma.rn.f32x2 %0, %1, %2, %0;" : "+l"(d) : "l"(a), "l"(b));
}
__device__ __forceinline__ void unpack2(float& lo, float& hi, unsigned long long v) {
    asm("mov.b64 {%0,%1}, %2;" : "=f"(lo), "=f"(hi) : "l"(v));
}
__device__ __forceinline__ unsigned long long pack2(float lo, float hi) {
    unsigned long long v;
    asm("mov.b64 %0, {%1,%2};" : "=l"(v) : "f"(lo), "f"(hi));
    return v;
}

// ---------------- preprocessing: CSR-by-target + degree terms ----------------
__global__ void k_init(int n) {
    int i = blockIdx.x * blockDim.x + threadIdx.x;
    if (i < n) d_cnt[i] = 0;
}

__global__ void k_hist(const int* __restrict__ col, int e, int n) {
    int i = blockIdx.x * blockDim.x + threadIdx.x;
    if (i < e) {
        int c = col[i];
        if (c >= 0 && c < n) atomicAdd(&d_cnt[c], 1);
    }
}

__global__ void k_scan1(int n) {
    __shared__ int s[1024];
    int t = threadIdx.x;
    int i = blockIdx.x * 1024 + t;
    s[t] = (i < n) ? d_cnt[i] : 0;
    __syncthreads();
    for (int off = 1; off < 1024; off <<= 1) {
        int a = 0;
        if (t >= off) a = s[t - off];
        __syncthreads();
        s[t] += a;
        __syncthreads();
    }
    if (i < n) d_incl[i] = s[t];
    if (t == 1023) d_bsum[blockIdx.x] = s[1023];
}

__global__ void k_scan2(int nb) {   // single warp, shfl scan with carry
    int lane = threadIdx.x;
    int carry = 0;
    for (int base = 0; base < nb; base += 32) {
        int i = base + lane;
        int own = (i < nb) ? d_bsum[i] : 0;
        int v = own;
        #pragma unroll
        for (int o = 1; o < 32; o <<= 1) {
            int t = __shfl_up_sync(0xffffffffu, v, o);
            if (lane >= o) v += t;
        }
        if (i < nb) d_bpref[i] = carry + v - own;   // exclusive
        carry += __shfl_sync(0xffffffffu, v, 31);
    }
}

__global__ void k_scan3(int n) {
    int i = blockIdx.x * blockDim.x + threadIdx.x;
    if (i >= n) return;
    int gi = d_incl[i] + d_bpref[i >> 10];
    int c  = d_cnt[i];
    int st = gi - c;
    d_rs[i] = st;
    d_cursor[i] = st;
    if (i == n - 1) d_rs[n] = gi;
    float deg = (float)(c + 1);          // degree incl. self-loop
    float di = rsqrtf(deg);
    d_dinv[i] = di;
    d_sc[i]   = di / deg;
}

__global__ void k_scatter(const int* __restrict__ ei, int e, int n) {
    int i = blockIdx.x * blockDim.x + threadIdx.x;
    if (i >= e) return;
    int c = ei[e + i];  // col (target)
    int r = ei[i];      // row (source)
    if (c < 0 || c >= n || r < 0 || r >= n) return;
    int pos = atomicAdd(&d_cursor[c], 1);
    d_csr[pos] = r;
}

// ---------------- W prep: transpose fp32 weights: wT[k][j] = W[j][k] ----------------
__global__ void __launch_bounds__(256) k_prepw(
    const float* __restrict__ Wa, const float* __restrict__ Wb,
    const float* __restrict__ Wc, const float* __restrict__ Wd)
{
    int l = blockIdx.x;
    const float* W = (l == 0) ? Wa : (l == 1) ? Wb : (l == 2) ? Wc : Wd;
    float* wT = d_wimgT[l];
    for (int idx = threadIdx.x; idx < 16384; idx += 256) {
        int k = idx >> 7, j = idx & 127;
        wT[idx] = W[j * 128 + k];
    }
}

// ---------------- packed-fp32 (FFMA2) GEMM: bufB = rs * (A @ W^T + bias), opt relu -------
// 128x128 tile/block, 256 threads, K in 2 chunks of 64.
// smem: bias[128] @0; AsDup[64][256] (A duplicated along row-dim) @512; BsT[64][128] @66048.
// Thread (tx=tid&15, ty=tid>>4): rows r=ty+16m (m=0..7), col pairs c={2tx+32q, +1} (q=0..3).
// acc[m][q] packed f32x2 over the column pair; a operand replicated via AsDup.
#define OFF_A   512
#define OFF_B   66048
#define SMEM_TOT 98816

__global__ void __launch_bounds__(256, 2) k_gemm_f2(
    const float* __restrict__ Aopt,        // nullptr -> d_bufA
    const float* __restrict__ wT,          // transposed W image [128][128]
    const float* __restrict__ bias,
    const float* __restrict__ colscale,    // nullptr or [128]
    int use_dinv, int relu, int n)
{
    extern __shared__ __align__(16) char sm[];
    uint32_t smb = smem_u32(sm);
    int tid = threadIdx.x;
    int tx = tid & 15, ty = tid >> 4;
    int row0 = blockIdx.x * 128;
    const float* A = Aopt ? Aopt : d_bufA;

    if (tid < 128) *(float*)(sm + tid * 4) = bias[tid];

    unsigned long long acc[8][4];
    #pragma unroll
    for (int m = 0; m < 8; ++m)
        #pragma unroll
        for (int q = 0; q < 4; ++q) acc[m][q] = 0ull;

    // per-thread smem byte bases for the compute loop
    uint32_t aB = smb + OFF_A + (uint32_t)ty * 8;     // + k*1024 + m*128
    uint32_t bB = smb + OFF_B + (uint32_t)tx * 8;     // + k*512  + q*128

    const float4* A4 = (const float4*)A;
    const float4* W4 = (const float4*)wT;

    for (int kc = 0; kc < 2; ++kc) {
        // ---- loaders ----
        if (tid < 128) {
            // A rows: thread owns row r=tid; 16 float4 (64 k), duplicated store
            int r = tid;
            int gr = row0 + r;
            float2* ad = (float2*)(sm + OFF_A);
            #pragma unroll
            for (int j = 0; j < 16; ++j) {
                float4 v = make_float4(0.f, 0.f, 0.f, 0.f);
                if (gr < n) v = A4[gr * 32 + kc * 16 + j];
                if (colscale) {
                    int cb = kc * 64 + j * 4;
                    v.x *= colscale[cb + 0];
                    v.y *= colscale[cb + 1];
                    v.z *= colscale[cb + 2];
                    v.w *= colscale[cb + 3];
                }
                int lk = j * 4;                       // local k of v.x
                ad[(lk + 0) * 128 + r] = make_float2(v.x, v.x);
                ad[(lk + 1) * 128 + r] = make_float2(v.y, v.y);
                ad[(lk + 2) * 128 + r] = make_float2(v.z, v.z);
                ad[(lk + 3) * 128 + r] = make_float2(v.w, v.w);
            }
        } else {
            // W chunk copy: 64 rows x 128 floats = 2048 float4, linear
            int t = tid - 128;
            float4* bd = (float4*)(sm + OFF_B);
            #pragma unroll
            for (int j = 0; j < 16; ++j) {
                int idx = t + j * 128;                // 0..2047
                bd[idx] = W4[kc * 2048 + idx];
            }
        }
        __syncthreads();

        // ---- compute 64 k-steps ----
        #pragma unroll 4
        for (int k = 0; k < 64; ++k) {
            uint32_t ak = aB + (uint32_t)k * 1024;
            uint32_t bk = bB + (uint32_t)k * 512;
            unsigned long long b0 = lds64(bk);
            unsigned long long b1 = lds64(bk + 128);
            unsigned long long b2 = lds64(bk + 256);
            unsigned long long b3 = lds64(bk + 384);
            #pragma unroll
            for (int m = 0; m < 8; ++m) {
                unsigned long long a = lds64(ak + (uint32_t)m * 128);
                ffma2(acc[m][0], a, b0);
                ffma2(acc[m][1], a, b1);
                ffma2(acc[m][2], a, b2);
                ffma2(acc[m][3], a, b3);
            }
        }
        __syncthreads();
    }

    // ---- epilogue: unpack, bias, rowscale, relu, float2 store ----
    const float* bs = (const float*)sm;
    #pragma unroll
    for (int m = 0; m < 8; ++m) {
        int gr = row0 + ty + 16 * m;
        if (gr >= n) continue;
        float rs = use_dinv ? d_dinv[gr] : 1.f;
        #pragma unroll
        for (int q = 0; q < 4; ++q) {
            int c = 2 * tx + 32 * q;
            float lo, hi;
            unpack2(lo, hi, acc[m][q]);
            float2 o;
            o.x = (lo + bs[c + 0]) * rs;
            o.y = (hi + bs[c + 1]) * rs;
            if (relu) { o.x = fmaxf(o.x, 0.f); o.y = fmaxf(o.y, 0.f); }
            *(float2*)(d_bufB + (size_t)gr * 128 + c) = o;
        }
    }
}

// ---------------- aggregation: bufA[c] = relu(sc[c]*(bufB[c]+sum bufB[src]) + bc) --------
__global__ void k_agg(const float* __restrict__ bc, int n)
{
    int w = (blockIdx.x * blockDim.x + threadIdx.x) >> 5;
    int lane = threadIdx.x & 31;
    if (w >= n) return;
    const float4* g = (const float4*)d_bufB;
    float4 s = g[w * 32 + lane];   // self-loop term
    int beg = d_rs[w], end = d_rs[w + 1];
    for (int e = beg; e < end; ++e) {
        int src = d_csr[e];
        float4 v = g[src * 32 + lane];
        s.x += v.x; s.y += v.y; s.z += v.z; s.w += v.w;
    }
    float kf = d_sc[w];
    float bx = bc[lane * 4 + 0], by = bc[lane * 4 + 1];
    float bz = bc[lane * 4 + 2], bw = bc[lane * 4 + 3];
    float4 o;
    o.x = fmaxf(kf * s.x + bx, 0.f);
    o.y = fmaxf(kf * s.y + by, 0.f);
    o.z = fmaxf(kf * s.z + bz, 0.f);
    o.w = fmaxf(kf * s.w + bw, 0.f);
    ((float4*)d_bufA)[w * 32 + lane] = o;
}

// ---------------- final linear (H=128 -> C=40) + log_softmax, one warp/row ----------------
__global__ void __launch_bounds__(256) k_lin2(
    const float* __restrict__ W2, const float* __restrict__ b2,
    float* __restrict__ out, int n)
{
    __shared__ __align__(16) float Ws[40 * 129];
    __shared__ __align__(16) float rowbuf[8][128];
    int tid = threadIdx.x;
    for (int idx = tid; idx < 40 * 128; idx += 256) {
        int c = idx >> 7, k = idx & 127;
        Ws[c * 129 + k] = W2[idx];
    }
    __syncthreads();

    int lane = tid & 31, w = tid >> 5;
    int row = blockIdx.x * 8 + w;
    if (row >= n) return;

    float4 hv = ((const float4*)d_bufB)[row * 32 + lane];
    rowbuf[w][lane * 4 + 0] = hv.x;
    rowbuf[w][lane * 4 + 1] = hv.y;
    rowbuf[w][lane * 4 + 2] = hv.z;
    rowbuf[w][lane * 4 + 3] = hv.w;
    __syncwarp();

    int c1 = 32 + (lane & 7);
    float v0 = b2[lane];
    float v1 = b2[c1];
    #pragma unroll 8
    for (int k = 0; k < 128; k++) {
        float hk = rowbuf[w][k];
        v0 += hk * Ws[lane * 129 + k];
        v1 += hk * Ws[c1 * 129 + k];
    }
    float m = fmaxf(v0, (lane < 8) ? v1 : -1e30f);
    #pragma unroll
    for (int o = 16; o; o >>= 1) m = fmaxf(m, __shfl_xor_sync(0xffffffffu, m, o));
    float e0 = __expf(v0 - m);
    float e1 = (lane < 8) ? __expf(v1 - m) : 0.f;
    float ssum = e0 + e1;
    #pragma unroll
    for (int o = 16; o; o >>= 1) ssum += __shfl_xor_sync(0xffffffffu, ssum, o);
    float ls = m + __logf(ssum);
    out[row * 40 + lane] = v0 - ls;
    if (lane < 8) out[row * 40 + 32 + lane] = v1 - ls;
}

// ---------------- launch ----------------
extern "C" void kernel_launch(void* const* d_in, const int* in_sizes, int n_in,
                              void* d_out, int out_size)
{
    const float* x    = (const float*)d_in[0];
    const int*   ei   = (const int*)d_in[1];     // int32 (JAX x64 disabled)
    const float* imp  = (const float*)d_in[2];
    const float* W1   = (const float*)d_in[3];
    const float* bl1  = (const float*)d_in[4];
    const float* bc1  = (const float*)d_in[5];
    const float* W2   = (const float*)d_in[6];
    const float* bl2  = (const float*)d_in[7];
    const float* bc2  = (const float*)d_in[8];
    const float* W3   = (const float*)d_in[9];
    const float* bl3  = (const float*)d_in[10];
    const float* bc3  = (const float*)d_in[11];
    const float* Wl1  = (const float*)d_in[12];
    const float* bli1 = (const float*)d_in[13];
    const float* Wl2  = (const float*)d_in[14];
    const float* bli2 = (const float*)d_in[15];
    int n = in_sizes[0] / HF;
    int e = in_sizes[1] / 2;
    float* out = (float*)d_out;

    cudaFuncSetAttribute(k_gemm_f2, cudaFuncAttributeMaxDynamicSharedMemorySize, SMEM_TOT);

    // preprocessing (CSR build + degree scaling) + W transposed images
    k_init   <<<(n + 255) / 256, 256>>>(n);
    k_hist   <<<(e + 255) / 256, 256>>>(ei + e, e, n);
    int nb = (n + 1023) / 1024;
    k_scan1  <<<nb, 1024>>>(n);
    k_scan2  <<<1, 32>>>(nb);
    k_scan3  <<<(n + 255) / 256, 256>>>(n);
    k_scatter<<<(e + 255) / 256, 256>>>(ei, e, n);
    k_prepw  <<<4, 256>>>(W1, W2, W3, Wl1);

    int gblocks = (n + 127) / 128;
    int ablocks = (n + 7) / 8;

    // conv1 (importance folded into A load; dinv rowscale in epilogue)
    k_gemm_f2<<<gblocks, 256, SMEM_TOT>>>(x,       d_wimgT[0], bl1,  imp,     1, 0, n);
    k_agg    <<<ablocks, 256>>>(bc1, n);
    // conv2
    k_gemm_f2<<<gblocks, 256, SMEM_TOT>>>(nullptr, d_wimgT[1], bl2,  nullptr, 1, 0, n);
    k_agg    <<<ablocks, 256>>>(bc2, n);
    // conv3
    k_gemm_f2<<<gblocks, 256, SMEM_TOT>>>(nullptr, d_wimgT[2], bl3,  nullptr, 1, 0, n);
    k_agg    <<<ablocks, 256>>>(bc3, n);
    // lin1 + relu
    k_gemm_f2<<<gblocks, 256, SMEM_TOT>>>(nullptr, d_wimgT[3], bli1, nullptr, 0, 1, n);
    // lin2 + log_softmax
    k_lin2   <<<ablocks, 256>>>(Wl2, bli2, out, n);
}

// round 7
// speedup vs baseline: 2.0972x; 1.7444x over previous
#include <cuda_runtime.h>
#include <cstdint>

#define N_MAX 100000
#define E_MAX 600000
#define HF 128

// ---------------- scratch (static __device__ — no allocation) ----------------
__device__ __align__(16) float d_bufA[N_MAX * HF];
__device__ __align__(16) float d_bufB[N_MAX * HF];
__device__ int   d_cnt[N_MAX];
__device__ int   d_incl[N_MAX];
__device__ int   d_rs[N_MAX + 1];
__device__ int   d_cursor[N_MAX];
__device__ int   d_csr[E_MAX];
__device__ float d_dinv[N_MAX];
__device__ float d_sc[N_MAX];     // dinv/deg
__device__ int   d_bsum[256];
__device__ int   d_bpref[256];

__device__ __forceinline__ uint32_t smem_u32(const void* p) {
    uint32_t a;
    asm("{ .reg .u64 t; cvta.to.shared.u64 t, %1; cvt.u32.u64 %0, t; }" : "=r"(a) : "l"(p));
    return a;
}
__device__ __forceinline__ void cpa16(uint32_t dst, const void* src, int ssz) {
    asm volatile("cp.async.ca.shared.global [%0], [%1], 16, %2;"
                 :: "r"(dst), "l"(src), "r"(ssz) : "memory");
}
__device__ __forceinline__ void cpa_commit() {
    asm volatile("cp.async.commit_group;" ::: "memory");
}
template <int N>
__device__ __forceinline__ void cpa_wait() {
    asm volatile("cp.async.wait_group %0;" :: "n"(N) : "memory");
}

// ---------------- preprocessing: CSR-by-target + degree terms ----------------
__global__ void k_hist(const int* __restrict__ col, int e, int n) {
    int i = blockIdx.x * blockDim.x + threadIdx.x;
    if (i < e) {
        int c = col[i];
        if (c >= 0 && c < n) atomicAdd(&d_cnt[c], 1);
    }
}

__global__ void k_scan1(int n) {
    __shared__ int s[1024];
    int t = threadIdx.x;
    int i = blockIdx.x * 1024 + t;
    s[t] = (i < n) ? d_cnt[i] : 0;
    __syncthreads();
    for (int off = 1; off < 1024; off <<= 1) {
        int a = 0;
        if (t >= off) a = s[t - off];
        __syncthreads();
        s[t] += a;
        __syncthreads();
    }
    if (i < n) d_incl[i] = s[t];
    if (t == 1023) d_bsum[blockIdx.x] = s[1023];
}

__global__ void k_scan2(int nb) {   // single warp, shfl scan with carry
    int lane = threadIdx.x;
    int carry = 0;
    for (int base = 0; base < nb; base += 32) {
        int i = base + lane;
        int own = (i < nb) ? d_bsum[i] : 0;
        int v = own;
        #pragma unroll
        for (int o = 1; o < 32; o <<= 1) {
            int t = __shfl_up_sync(0xffffffffu, v, o);
            if (lane >= o) v += t;
        }
        if (i < nb) d_bpref[i] = carry + v - own;   // exclusive
        carry += __shfl_sync(0xffffffffu, v, 31);
    }
}

__global__ void k_scan3(int n) {
    int i = blockIdx.x * blockDim.x + threadIdx.x;
    if (i >= n) return;
    int gi = d_incl[i] + d_bpref[i >> 10];
    int c  = d_cnt[i];
    d_cnt[i] = 0;                        // re-zero for next graph replay
    int st = gi - c;
    d_rs[i] = st;
    d_cursor[i] = st;
    if (i == n - 1) d_rs[n] = gi;
    float deg = (float)(c + 1);          // degree incl. self-loop
    float di = rsqrtf(deg);
    d_dinv[i] = di;
    d_sc[i]   = di / deg;
}

__global__ void k_scatter(const int* __restrict__ ei, int e, int n) {
    int i = blockIdx.x * blockDim.x + threadIdx.x;
    if (i >= e) return;
    int c = ei[e + i];  // col (target)
    int r = ei[i];      // row (source)
    if (c < 0 || c >= n || r < 0 || r >= n) return;
    int pos = atomicAdd(&d_cursor[c], 1);
    d_csr[pos] = r;
}

// ---------------- prescale: bufA = x * importance ----------------
__global__ void k_scale(const float4* __restrict__ x4, const float* __restrict__ imp, int n4) {
    int i = blockIdx.x * blockDim.x + threadIdx.x;
    if (i >= n4) return;
    float4 v = x4[i];
    int c = (i & 31) * 4;
    v.x *= imp[c + 0];
    v.y *= imp[c + 1];
    v.z *= imp[c + 2];
    v.w *= imp[c + 3];
    ((float4*)d_bufA)[i] = v;
}

// ---------------- fp32 GEMM with cp.async pipeline ----------------
// d_bufB = rowscale * (d_bufA @ W^T + bias), optional relu.
// 128x128 tile, 256 threads, 8x8 microtile. W loaded ONCE transposed+XOR-swizzled
// (Bs[k][j^(k&31)]); A in 32-k chunks, double-buffered via cp.async.
// smem: Bs 64KB @0; As[2][128][36] @65536 (pitch 36 floats = 144B, 16B-aligned rows).
#define OFF_AS  65536
#define APITCH  36
#define ASTAGE  (128 * APITCH * 4)          // 18432 B
#define GEMM_SMEM (OFF_AS + 2 * ASTAGE)     // 102400 B

__global__ void __launch_bounds__(256, 2) k_gemm(
    const float* __restrict__ W,
    const float* __restrict__ bias,
    int use_dinv, int relu, int n)
{
    extern __shared__ __align__(16) char sm[];
    uint32_t smb = smem_u32(sm);
    float* Bs = (float*)sm;
    int tid = threadIdx.x;
    int tx = tid & 15, ty = tid >> 4;
    int row0 = blockIdx.x * 128;
    const float* A = d_bufA;

    // ---- prefetch A chunk 0 (overlaps with Bs transpose below) ----
    {
        #pragma unroll
        for (int t = 0; t < 4; ++t) {
            int idx = tid + t * 256;            // 0..1023
            int r = idx >> 3, c4 = idx & 7;
            int gr = row0 + r;
            uint32_t dst = smb + OFF_AS + (uint32_t)(r * 144 + c4 * 16);
            cpa16(dst, A + (size_t)gr * 128 + c4 * 4, gr < n ? 16 : 0);
        }
        cpa_commit();
    }

    // ---- load full W transposed with XOR swizzle: Bs[k][j ^ (k&31)] = W[j][k] ----
    {
        const float4* W4 = (const float4*)W;
        #pragma unroll
        for (int it = 0; it < 16; ++it) {
            int idx = tid + it * 256;           // 0..4095
            int j = idx >> 5, kq = idx & 31;
            float4 v = W4[j * 32 + kq];
            int k0 = kq * 4;
            Bs[(k0 + 0) * 128 + (j ^ ((k0 + 0) & 31))] = v.x;
            Bs[(k0 + 1) * 128 + (j ^ ((k0 + 1) & 31))] = v.y;
            Bs[(k0 + 2) * 128 + (j ^ ((k0 + 2) & 31))] = v.z;
            Bs[(k0 + 3) * 128 + (j ^ ((k0 + 3) & 31))] = v.w;
        }
    }

    float acc[8][8];
    #pragma unroll
    for (int i = 0; i < 8; i++)
        #pragma unroll
        for (int j = 0; j < 8; j++) acc[i][j] = 0.f;

    for (int kc = 0; kc < 4; ++kc) {
        // prefetch next chunk into alternate stage
        if (kc < 3) {
            #pragma unroll
            for (int t = 0; t < 4; ++t) {
                int idx = tid + t * 256;
                int r = idx >> 3, c4 = idx & 7;
                int gr = row0 + r;
                uint32_t dst = smb + OFF_AS + (uint32_t)(((kc + 1) & 1) * ASTAGE)
                             + (uint32_t)(r * 144 + c4 * 16);
                cpa16(dst, A + (size_t)gr * 128 + (kc + 1) * 32 + c4 * 4, gr < n ? 16 : 0);
            }
            cpa_commit();
            cpa_wait<1>();      // current chunk complete, next in flight
        } else {
            cpa_wait<0>();
        }
        __syncthreads();

        const float* As = (const float*)(sm + OFF_AS + (kc & 1) * ASTAGE);
        #pragma unroll 4
        for (int kl = 0; kl < 32; ++kl) {
            int k = kc * 32 + kl;
            int f = k & 31;
            float a[8], b[8];
            #pragma unroll
            for (int ii = 0; ii < 8; ii++) a[ii] = As[(ty + ii * 16) * APITCH + kl];
            #pragma unroll
            for (int jj = 0; jj < 8; jj++) b[jj] = Bs[k * 128 + ((tx + jj * 16) ^ f)];
            #pragma unroll
            for (int ii = 0; ii < 8; ii++)
                #pragma unroll
                for (int jj = 0; jj < 8; jj++)
                    acc[ii][jj] += a[ii] * b[jj];
        }
        __syncthreads();
    }

    #pragma unroll
    for (int ii = 0; ii < 8; ii++) {
        int gr = row0 + ty + ii * 16;
        if (gr >= n) continue;
        float rs = use_dinv ? d_dinv[gr] : 1.f;
        #pragma unroll
        for (int jj = 0; jj < 8; jj++) {
            int jc = tx + jj * 16;
            float v = (acc[ii][jj] + bias[jc]) * rs;
            if (relu) v = fmaxf(v, 0.f);
            d_bufB[(size_t)gr * 128 + jc] = v;
        }
    }
}

// ---------------- aggregation: bufA[c] = relu(sc[c]*(bufB[c]+sum bufB[src]) + bc) --------
__global__ void k_agg(const float* __restrict__ bc, int n)
{
    int w = (blockIdx.x * blockDim.x + threadIdx.x) >> 5;
    int lane = threadIdx.x & 31;
    if (w >= n) return;
    const float4* g = (const float4*)d_bufB;
    float4 s = g[w * 32 + lane];   // self-loop term
    int beg = d_rs[w], end = d_rs[w + 1];
    for (int e = beg; e < end; ++e) {
        int src = d_csr[e];
        float4 v = g[src * 32 + lane];
        s.x += v.x; s.y += v.y; s.z += v.z; s.w += v.w;
    }
    float kf = d_sc[w];
    float bx = bc[lane * 4 + 0], by = bc[lane * 4 + 1];
    float bz = bc[lane * 4 + 2], bw = bc[lane * 4 + 3];
    float4 o;
    o.x = fmaxf(kf * s.x + bx, 0.f);
    o.y = fmaxf(kf * s.y + by, 0.f);
    o.z = fmaxf(kf * s.z + bz, 0.f);
    o.w = fmaxf(kf * s.w + bw, 0.f);
    ((float4*)d_bufA)[w * 32 + lane] = o;
}

// ---------------- final linear (H=128 -> C=40) + log_softmax, one THREAD per row ----------
// smem: rowt[128][132] @0 (67584B), Ws2[128][40] k-major @67584 (20480B). 2 CTAs/SM.
#define L2_ROWT  0
#define L2_WS    67584
#define L2_SMEM  88064

__global__ void __launch_bounds__(128, 2) k_lin2(
    const float* __restrict__ W2, const float* __restrict__ b2,
    float* __restrict__ out, int n)
{
    extern __shared__ __align__(16) char sm[];
    float* rowt = (float*)(sm + L2_ROWT);    // pitch 132
    float* Ws2  = (float*)(sm + L2_WS);      // Ws2[k*40 + c] = W2[c*128 + k]
    int tid = threadIdx.x;
    int row0 = blockIdx.x * 128;

    // load W2 transposed (k-major for broadcast)
    for (int idx = tid; idx < 40 * 128; idx += 128) {
        int c = idx >> 7, k = idx & 127;
        Ws2[k * 40 + c] = W2[idx];
    }
    // load 128-row tile coalesced
    {
        const float4* h4 = (const float4*)d_bufB;
        #pragma unroll
        for (int it = 0; it < 32; ++it) {
            int idx = tid + it * 128;            // 0..4095
            int r = idx >> 5, c4 = idx & 31;
            float4 v = make_float4(0.f, 0.f, 0.f, 0.f);
            int gr = row0 + r;
            if (gr < n) v = h4[(size_t)gr * 32 + c4];
            *(float4*)(rowt + r * 132 + c4 * 4) = v;
        }
    }
    __syncthreads();

    int row = row0 + tid;
    if (row >= n) return;

    float acc[40];
    #pragma unroll
    for (int c = 0; c < 40; ++c) acc[c] = b2[c];

    const float* myrow = rowt + tid * 132;
    #pragma unroll 4
    for (int k = 0; k < 128; ++k) {
        float a = myrow[k];
        const float* wk = Ws2 + k * 40;
        #pragma unroll
        for (int c = 0; c < 40; ++c) acc[c] += a * wk[c];
    }

    // log_softmax over the 40 register values
    float m = acc[0];
    #pragma unroll
    for (int c = 1; c < 40; ++c) m = fmaxf(m, acc[c]);
    float ssum = 0.f;
    #pragma unroll
    for (int c = 0; c < 40; ++c) ssum += __expf(acc[c] - m);
    float ls = m + __logf(ssum);

    float4* o4 = (float4*)(out + (size_t)row * 40);
    #pragma unroll
    for (int q = 0; q < 10; ++q) {
        float4 o;
        o.x = acc[q * 4 + 0] - ls;
        o.y = acc[q * 4 + 1] - ls;
        o.z = acc[q * 4 + 2] - ls;
        o.w = acc[q * 4 + 3] - ls;
        o4[q] = o;
    }
}

// ---------------- launch ----------------
extern "C" void kernel_launch(void* const* d_in, const int* in_sizes, int n_in,
                              void* d_out, int out_size)
{
    const float* x    = (const float*)d_in[0];
    const int*   ei   = (const int*)d_in[1];     // int32 (JAX x64 disabled)
    const float* imp  = (const float*)d_in[2];
    const float* W1   = (const float*)d_in[3];
    const float* bl1  = (const float*)d_in[4];
    const float* bc1  = (const float*)d_in[5];
    const float* W2   = (const float*)d_in[6];
    const float* bl2  = (const float*)d_in[7];
    const float* bc2  = (const float*)d_in[8];
    const float* W3   = (const float*)d_in[9];
    const float* bl3  = (const float*)d_in[10];
    const float* bc3  = (const float*)d_in[11];
    const float* Wl1  = (const float*)d_in[12];
    const float* bli1 = (const float*)d_in[13];
    const float* Wl2  = (const float*)d_in[14];
    const float* bli2 = (const float*)d_in[15];
    int n = in_sizes[0] / HF;
    int e = in_sizes[1] / 2;
    float* out = (float*)d_out;

    cudaFuncSetAttribute(k_gemm, cudaFuncAttributeMaxDynamicSharedMemorySize, GEMM_SMEM);
    cudaFuncSetAttribute(k_lin2, cudaFuncAttributeMaxDynamicSharedMemorySize, L2_SMEM);

    // preprocessing: CSR build + degree scaling + x*importance prescale
    k_scale  <<<(n * 32 + 255) / 256, 256>>>((const float4*)x, imp, n * 32);
    k_hist   <<<(e + 255) / 256, 256>>>(ei + e, e, n);
    int nb = (n + 1023) / 1024;
    k_scan1  <<<nb, 1024>>>(n);
    k_scan2  <<<1, 32>>>(nb);
    k_scan3  <<<(n + 255) / 256, 256>>>(n);
    k_scatter<<<(e + 255) / 256, 256>>>(ei, e, n);

    int gblocks = (n + 127) / 128;
    int ablocks = (n + 7) / 8;

    // conv1 (x*importance already in bufA; dinv rowscale in epilogue)
    k_gemm<<<gblocks, 256, GEMM_SMEM>>>(W1,  bl1,  1, 0, n);
    k_agg <<<ablocks, 256>>>(bc1, n);
    // conv2
    k_gemm<<<gblocks, 256, GEMM_SMEM>>>(W2,  bl2,  1, 0, n);
    k_agg <<<ablocks, 256>>>(bc2, n);
    // conv3
    k_gemm<<<gblocks, 256, GEMM_SMEM>>>(W3,  bl3,  1, 0, n);
    k_agg <<<ablocks, 256>>>(bc3, n);
    // lin1 + relu
    k_gemm<<<gblocks, 256, GEMM_SMEM>>>(Wl1, bli1, 0, 1, n);
    // lin2 + log_softmax
    k_lin2<<<gblocks, 128, L2_SMEM>>>(Wl2, bli2, out, n);
}